// round 2
// baseline (speedup 1.0000x reference)
#include <cuda_runtime.h>

// MaxPool 2x2 stride 2, (16,64,512,512) fp32 -> (16,64,256,256) fp32.
// Pure HBM stream. Each thread produces 2 consecutive output float4
// (8 pooled values) from 8 front-batched LDG.128 (64B contiguous per input
// row per thread), with streaming (evict-first) cache hints on both loads
// and stores since every byte is touched exactly once.

#define IN_H 512
#define OUT_H 256
#define BC (16 * 64)

#define IN_ROW_F4 128   // 512 floats / 4
#define OUT_ROW_F4 64   // 256 floats / 4
#define OUT_F4_PER_THREAD 2

__global__ void maxpool2x2_kernel(const float4* __restrict__ in4,
                                  float4* __restrict__ out4) {
    // total output float4 = 1024*256*64 = 16,777,216; threads = total/2 = 8,388,608
    unsigned tid = blockIdx.x * blockDim.x + threadIdx.x;

    // Each thread owns output f4 indices [2*tid, 2*tid+1].
    unsigned opos = tid * OUT_F4_PER_THREAD;          // output float4 index
    unsigned ox4  = opos & (OUT_ROW_F4 - 1);          // [0,64), even
    unsigned rest = opos >> 6;
    unsigned oy   = rest & (OUT_H - 1);               // [0,256)
    unsigned bc   = rest >> 8;                        // [0,1024)

    // Input: row pair (2*oy, 2*oy+1), starting at float4 col 2*ox4, 4 consecutive f4 per row.
    unsigned ibase = bc * (IN_H * IN_ROW_F4) + (oy * 2) * IN_ROW_F4 + ox4 * 2;

    // Front-batch all 8 loads (MLP=8), 64B contiguous per row per thread.
    float4 a0 = __ldcs(&in4[ibase + 0]);
    float4 a1 = __ldcs(&in4[ibase + 1]);
    float4 a2 = __ldcs(&in4[ibase + 2]);
    float4 a3 = __ldcs(&in4[ibase + 3]);
    float4 b0 = __ldcs(&in4[ibase + IN_ROW_F4 + 0]);
    float4 b1 = __ldcs(&in4[ibase + IN_ROW_F4 + 1]);
    float4 b2 = __ldcs(&in4[ibase + IN_ROW_F4 + 2]);
    float4 b3 = __ldcs(&in4[ibase + IN_ROW_F4 + 3]);

    float4 o0, o1;
    o0.x = fmaxf(fmaxf(a0.x, a0.y), fmaxf(b0.x, b0.y));
    o0.y = fmaxf(fmaxf(a0.z, a0.w), fmaxf(b0.z, b0.w));
    o0.z = fmaxf(fmaxf(a1.x, a1.y), fmaxf(b1.x, b1.y));
    o0.w = fmaxf(fmaxf(a1.z, a1.w), fmaxf(b1.z, b1.w));
    o1.x = fmaxf(fmaxf(a2.x, a2.y), fmaxf(b2.x, b2.y));
    o1.y = fmaxf(fmaxf(a2.z, a2.w), fmaxf(b2.z, b2.w));
    o1.z = fmaxf(fmaxf(a3.x, a3.y), fmaxf(b3.x, b3.y));
    o1.w = fmaxf(fmaxf(a3.z, a3.w), fmaxf(b3.z, b3.w));

    __stcs(&out4[opos + 0], o0);
    __stcs(&out4[opos + 1], o1);
}

extern "C" void kernel_launch(void* const* d_in, const int* in_sizes, int n_in,
                              void* d_out, int out_size) {
    const float4* in4 = (const float4*)d_in[0];
    float4* out4 = (float4*)d_out;

    const unsigned total_threads = (unsigned)BC * OUT_H * OUT_ROW_F4 / OUT_F4_PER_THREAD; // 8,388,608
    const int threads = 256;
    const unsigned blocks = total_threads / threads;  // 32,768

    maxpool2x2_kernel<<<blocks, threads>>>(in4, out4);
}

// round 3
// speedup vs baseline: 1.0087x; 1.0087x over previous
#include <cuda_runtime.h>

// MaxPool 2x2 stride 2, (16,64,512,512) fp32 -> (16,64,256,256) fp32.
// Pure HBM stream at the DRAM roofline. Layout goal: every LDG.128 wavefront
// touches fully-utilized 128B lines (consecutive lanes -> consecutive float4),
// minimizing L1tex wavefronts per instruction.
//
// Each warp owns a 64-float4 column chunk of an input row PAIR:
//   lane loads row0[c+lane], row0[c+lane+32], row1[c+lane], row1[c+lane+32]
// Each input float4 + its vertical partner pool into one float2 output,
// stored lane-consecutive (coalesced STG.64).

#define IN_H 512
#define OUT_H 256
#define BC (16 * 64)

#define IN_ROW_F4 128    // 512 floats / 4
#define OUT_ROW_F2 128   // 256 floats / 2

__global__ void maxpool2x2_kernel(const float4* __restrict__ in4,
                                  float2* __restrict__ out2) {
    unsigned tid = blockIdx.x * blockDim.x + threadIdx.x;
    unsigned lane = tid & 31;
    unsigned chunk = tid >> 5;              // global warp id

    // 2 chunks (of 64 f4) per input row pair
    unsigned half = chunk & 1;              // which 64-f4 half of the row
    unsigned rest = chunk >> 1;
    unsigned rp   = rest & (OUT_H - 1);     // row pair index = output row [0,256)
    unsigned bc   = rest >> 8;              // plane [0,1024)

    unsigned ibase = bc * (IN_H * IN_ROW_F4) + (rp * 2) * IN_ROW_F4 + half * 64 + lane;

    // Front-batched, fully-coalesced loads (each wavefront = 4 full lines).
    float4 r0a = __ldcs(&in4[ibase]);
    float4 r0b = __ldcs(&in4[ibase + 32]);
    float4 r1a = __ldcs(&in4[ibase + IN_ROW_F4]);
    float4 r1b = __ldcs(&in4[ibase + IN_ROW_F4 + 32]);

    float2 o0, o1;
    o0.x = fmaxf(fmaxf(r0a.x, r0a.y), fmaxf(r1a.x, r1a.y));
    o0.y = fmaxf(fmaxf(r0a.z, r0a.w), fmaxf(r1a.z, r1a.w));
    o1.x = fmaxf(fmaxf(r0b.x, r0b.y), fmaxf(r1b.x, r1b.y));
    o1.y = fmaxf(fmaxf(r0b.z, r0b.w), fmaxf(r1b.z, r1b.w));

    unsigned obase = bc * (OUT_H * OUT_ROW_F2) + rp * OUT_ROW_F2 + half * 64 + lane;
    __stcs(&out2[obase], o0);
    __stcs(&out2[obase + 32], o1);
}

extern "C" void kernel_launch(void* const* d_in, const int* in_sizes, int n_in,
                              void* d_out, int out_size) {
    const float4* in4 = (const float4*)d_in[0];
    float2* out2 = (float2*)d_out;

    // total threads = chunks * 32 = (1024 planes * 256 row-pairs * 2 halves) * 32
    const unsigned total_threads = (unsigned)BC * OUT_H * 2 * 32;  // 16,777,216
    const int threads = 256;
    const unsigned blocks = total_threads / threads;               // 65,536

    maxpool2x2_kernel<<<blocks, threads>>>(in4, out2);
}